// round 10
// baseline (speedup 1.0000x reference)
#include <cuda_runtime.h>
#include <math.h>

// Fixed shapes: x (4, 32, 8192, 64) fp32, token_positions = arange(8192)
#define SEQ        8192
#define NF4_ROW    16                    // 64 floats / 4 per row
#define SLICE_F4   (SEQ * NF4_ROW)       // 131072 float4 per (b,h) slice
#define N4_TOTAL   (128 * SLICE_F4)      // 16,777,216 float4 total
#define QUARTER_F4 (N4_TOTAL / 4)        // = 32 * SLICE_F4 -> same (p,j)
#define LOG2_THETA 13.2877123795494489f  // log2(10000), fp32

// R9 structure (no smem, no barrier, no prologue; loads front-batched before
// inline trig) widened to ILP=4. All four streams are exact slice-multiples
// apart, so they share one {c0,s0,c1,s1} set: trig per byte is halved vs R9.
__global__ void __launch_bounds__(256, 6)
rope_inline4(const float4* __restrict__ x, float4* __restrict__ out,
             const int* __restrict__ pos) {
    int i = blockIdx.x * 256 + threadIdx.x;      // 0 .. QUARTER_F4-1
    int j = i & (NF4_ROW - 1);                   // float4 within row
    int p = (i >> 4) & (SEQ - 1);                // seq position

    // ---- Front-batch all 4 loads: DRAM latency covers the trig below ----
    float4 v0 = x[i];
    float4 v1 = x[i + 1 * QUARTER_F4];
    float4 v2 = x[i + 2 * QUARTER_F4];
    float4 v3 = x[i + 3 * QUARTER_F4];

    // ---- Inline trig for pairs k = 2j, 2j+1 (shared by all 4 streams) ----
    float posf = (float)__ldg(&pos[p]);
    float invf0 = exp2f(-(float)(2 * j)     * (LOG2_THETA / 32.0f));
    float invf1 = exp2f(-(float)(2 * j + 1) * (LOG2_THETA / 32.0f));
    float c0, s0, c1, s1;
    sincosf(posf * invf0, &s0, &c0);
    sincosf(posf * invf1, &s1, &c1);

    // ---- Rotate + store ----
    float4 o;
    o.x = c0 * v0.x - s0 * v0.y;  o.y = s0 * v0.x + c0 * v0.y;
    o.z = c1 * v0.z - s1 * v0.w;  o.w = s1 * v0.z + c1 * v0.w;
    out[i] = o;
    o.x = c0 * v1.x - s0 * v1.y;  o.y = s0 * v1.x + c0 * v1.y;
    o.z = c1 * v1.z - s1 * v1.w;  o.w = s1 * v1.z + c1 * v1.w;
    out[i + 1 * QUARTER_F4] = o;
    o.x = c0 * v2.x - s0 * v2.y;  o.y = s0 * v2.x + c0 * v2.y;
    o.z = c1 * v2.z - s1 * v2.w;  o.w = s1 * v2.z + c1 * v2.w;
    out[i + 2 * QUARTER_F4] = o;
    o.x = c0 * v3.x - s0 * v3.y;  o.y = s0 * v3.x + c0 * v3.y;
    o.z = c1 * v3.z - s1 * v3.w;  o.w = s1 * v3.z + c1 * v3.w;
    out[i + 3 * QUARTER_F4] = o;
}

extern "C" void kernel_launch(void* const* d_in, const int* in_sizes, int n_in,
                              void* d_out, int out_size) {
    const float4* x   = (const float4*)d_in[0];
    const int*    pos = (const int*)d_in[1];
    float4*       out = (float4*)d_out;

    // 4,194,304 threads = 16384 blocks of 256
    rope_inline4<<<QUARTER_F4 / 256, 256>>>(x, out, pos);
}

// round 11
// speedup vs baseline: 1.0004x; 1.0004x over previous
#include <cuda_runtime.h>
#include <math.h>

// Fixed shapes: x (4, 32, 8192, 64) fp32, token_positions = arange(8192)
#define SEQ       8192
#define NF4_ROW   16                    // 64 floats / 4 per row
#define SLICE_F4  (SEQ * NF4_ROW)       // 131072 float4 per (b,h) slice
#define N4_TOTAL  (128 * SLICE_F4)      // 16,777,216 float4 total
#define HALF_F4   (N4_TOTAL / 2)        // = 64 * SLICE_F4 -> same (p,j)
#define LOG2_THETA 13.2877123795494489f // log2(10000), fp32

// R9 (best DRAM%: 82.6) with two tweaks:
//  - __ldcg on the streaming x loads (bypass L1; zero reuse, frees L1 for
//    the store path). NOT .cs — R8 showed L2 evict-first hurts.
//  - (256,8): R9 compiled to 28 regs, so the 32-reg cap is free and
//    guarantees 8 resident blocks/SM.
__global__ void __launch_bounds__(256, 8)
rope_inline(const float4* __restrict__ x, float4* __restrict__ out,
            const int* __restrict__ pos) {
    int i = blockIdx.x * 256 + threadIdx.x;      // 0 .. HALF_F4-1
    int j = i & (NF4_ROW - 1);                   // float4 within row
    int p = (i >> 4) & (SEQ - 1);                // seq position

    // ---- Front-batch both loads: DRAM latency covers the trig below ----
    float4 v0 = __ldcg(&x[i]);
    float4 v1 = __ldcg(&x[i + HALF_F4]);

    // ---- Inline trig for pairs k = 2j, 2j+1 (shared by both streams) ----
    float posf = (float)__ldg(&pos[p]);
    float invf0 = exp2f(-(float)(2 * j)     * (LOG2_THETA / 32.0f));
    float invf1 = exp2f(-(float)(2 * j + 1) * (LOG2_THETA / 32.0f));
    float c0, s0, c1, s1;
    sincosf(posf * invf0, &s0, &c0);
    sincosf(posf * invf1, &s1, &c1);

    // ---- Rotate + store ----
    float4 o;
    o.x = c0 * v0.x - s0 * v0.y;  o.y = s0 * v0.x + c0 * v0.y;
    o.z = c1 * v0.z - s1 * v0.w;  o.w = s1 * v0.z + c1 * v0.w;
    out[i] = o;
    o.x = c0 * v1.x - s0 * v1.y;  o.y = s0 * v1.x + c0 * v1.y;
    o.z = c1 * v1.z - s1 * v1.w;  o.w = s1 * v1.z + c1 * v1.w;
    out[i + HALF_F4] = o;
}

extern "C" void kernel_launch(void* const* d_in, const int* in_sizes, int n_in,
                              void* d_out, int out_size) {
    const float4* x   = (const float4*)d_in[0];
    const int*    pos = (const int*)d_in[1];
    float4*       out = (float4*)d_out;

    // 8,388,608 threads = 32768 blocks of 256
    rope_inline<<<HALF_F4 / 256, 256>>>(x, out, pos);
}